// round 2
// baseline (speedup 1.0000x reference)
#include <cuda_runtime.h>

#define N_FRAMES 16384
#define NUM_BIN  257
#define NUM_CH   8
#define TOTAL    (N_FRAMES * NUM_BIN)

__global__ __launch_bounds__(256) void beamform_kernel(
    const float* __restrict__ x,    // [16384, 2, 257, 8]
    const float* __restrict__ W,    // [24, 2, 257, 8]
    const int* __restrict__ beam,   // [16384]  (jax int64 -> int32 without x64)
    float* __restrict__ out)        // [16384, 2, 257, 1]
{
    int idx = blockIdx.x * blockDim.x + threadIdx.x;
    if (idx >= TOTAL) return;
    int t   = idx / NUM_BIN;
    int bin = idx - t * NUM_BIN;
    int b   = __ldg(beam + t);

    // base offsets (in floats); each row of 8 ch = 32 bytes, float4-aligned
    size_t x_base = ((size_t)t * 2 * NUM_BIN + bin) * NUM_CH;       // xr
    size_t w_base = ((size_t)b * 2 * NUM_BIN + bin) * NUM_CH;       // wr
    const float4* xr = (const float4*)(x + x_base);
    const float4* xi = (const float4*)(x + x_base + (size_t)NUM_BIN * NUM_CH);
    const float4* wr = (const float4*)(W + w_base);
    const float4* wi = (const float4*)(W + w_base + (size_t)NUM_BIN * NUM_CH);

    float4 xr0 = __ldg(xr), xr1 = __ldg(xr + 1);
    float4 xi0 = __ldg(xi), xi1 = __ldg(xi + 1);
    float4 wr0 = __ldg(wr), wr1 = __ldg(wr + 1);
    float4 wi0 = __ldg(wi), wi1 = __ldg(wi + 1);

    float out_r =
        xr0.x * wr0.x + xr0.y * wr0.y + xr0.z * wr0.z + xr0.w * wr0.w +
        xr1.x * wr1.x + xr1.y * wr1.y + xr1.z * wr1.z + xr1.w * wr1.w +
        xi0.x * wi0.x + xi0.y * wi0.y + xi0.z * wi0.z + xi0.w * wi0.w +
        xi1.x * wi1.x + xi1.y * wi1.y + xi1.z * wi1.z + xi1.w * wi1.w;

    float out_i =
        xi0.x * wr0.x + xi0.y * wr0.y + xi0.z * wr0.z + xi0.w * wr0.w +
        xi1.x * wr1.x + xi1.y * wr1.y + xi1.z * wr1.z + xi1.w * wr1.w -
        (xr0.x * wi0.x + xr0.y * wi0.y + xr0.z * wi0.z + xr0.w * wi0.w +
         xr1.x * wi1.x + xr1.y * wi1.y + xr1.z * wi1.z + xr1.w * wi1.w);

    size_t o_base = (size_t)t * 2 * NUM_BIN + bin;
    out[o_base] = out_r;
    out[o_base + NUM_BIN] = out_i;
}

extern "C" void kernel_launch(void* const* d_in, const int* in_sizes, int n_in,
                              void* d_out, int out_size) {
    const float* x    = (const float*)d_in[0];
    const float* W    = (const float*)d_in[1];
    const int*   beam = (const int*)d_in[2];
    float*       out  = (float*)d_out;

    int threads = 256;
    int blocks = (TOTAL + threads - 1) / threads;
    beamform_kernel<<<blocks, threads>>>(x, W, beam, out);
}